// round 9
// baseline (speedup 1.0000x reference)
#include <cuda_runtime.h>
#include <cstdint>

#define B 8
#define N 2048
#define BN (B * N)
#define DELTA 1e-7f

#define TPB 512
#define CROWS 8                         // rows per chunk: 8*2048*4B = 64KB contiguous
#define CHUNK_FLOATS (CROWS * N)        // 16384 floats
#define CHUNK_BYTES (CHUNK_FLOATS * 4)  // 65536
#define NCHUNKS (N / CROWS)             // 256 chunks per batch
#define CTAS_PER_B 19
#define GRID (B * CTAS_PER_B)           // 152 CTAs = GB300 SM count
#define STAGES 3
#define MAXCH ((NCHUNKS + CTAS_PER_B - 1) / CTAS_PER_B)   // 14

// Persistent scratch (__device__ globals per allocation rules).
__device__ float  g_odout1[BN];
__device__ float  g_odout2[BN];
__device__ float  g_pop1[BN];
__device__ float4 g_sir6[BN * 2];   // SIR after iter 0 (6 floats in 2x float4)
__device__ float  g_colA[BN * 4];   // iter0 colsums [OD_in, SIR_in*3] (zeroed by pass2)
__device__ float  g_colB[BN * 8];   // iter1 colsums [OD_in, SIR_in*6, pad] (zeroed by final)

__device__ __forceinline__ float dnn(float n, float d) { return (d == 0.0f) ? 0.0f : n / d; }

__device__ __forceinline__ uint32_t smem_u32(const void* p) {
    return (uint32_t)__cvta_generic_to_shared(p);
}
__device__ __forceinline__ void mbar_init(uint32_t a, uint32_t cnt) {
    asm volatile("mbarrier.init.shared.b64 [%0], %1;" :: "r"(a), "r"(cnt) : "memory");
}
__device__ __forceinline__ void mbar_expect_tx(uint32_t a, uint32_t bytes) {
    asm volatile("mbarrier.arrive.expect_tx.shared.b64 _, [%0], %1;"
                 :: "r"(a), "r"(bytes) : "memory");
}
__device__ __forceinline__ void mbar_wait(uint32_t a, uint32_t parity) {
    asm volatile(
        "{\n\t.reg .pred P;\n"
        "WAIT_%=:\n\t"
        "mbarrier.try_wait.parity.acquire.cta.shared::cta.b64 P, [%0], %1, 0x989680;\n\t"
        "@P bra DONE_%=;\n\t"
        "bra WAIT_%=;\n"
        "DONE_%=:\n\t}"
        :: "r"(a), "r"(parity) : "memory");
}
// 1D bulk async copy gmem->smem, completion via mbarrier complete_tx
__device__ __forceinline__ void tma_bulk_1d(uint32_t dst, const void* src,
                                            uint32_t bytes, uint32_t mbar) {
    asm volatile(
        "cp.async.bulk.shared::cta.global.mbarrier::complete_tx::bytes [%0], [%1], %2, [%3];"
        :: "r"(dst), "l"(src), "r"(bytes), "r"(mbar) : "memory");
}

// ---------------------------------------------------------------------------
// Pass 1 (iteration 0, K=4). TMA ring + FMA offset by one chunk.
// ---------------------------------------------------------------------------
__global__ void __launch_bounds__(TPB, 1) pass1_kernel(
    const float* __restrict__ inp, const float* __restrict__ od_all)
{
    extern __shared__ float sm[];
    float*     bufs   = sm;                                  // [3][16384]
    float*     s_part = sm + STAGES * CHUNK_FLOATS;          // [CROWS*TPB]
    float4*    s_w    = reinterpret_cast<float4*>(s_part + CROWS * TPB); // [2][CROWS]
    float4*    s_st   = s_w + 2 * CROWS;                     // [MAXCH*CROWS]
    uint64_t*  mbar   = reinterpret_cast<uint64_t*>(s_st + MAXCH * CROWS); // [3]

    const int b    = blockIdx.x / CTAS_PER_B;
    const int slot = blockIdx.x % CTAS_PER_B;
    const int tid  = threadIdx.x;
    const int warp = tid >> 5, lane = tid & 31;
    const float* OD = od_all + (size_t)(b * 2) * N * N;
    const int nch = (NCHUNKS - 1 - slot) / CTAS_PER_B + 1;   // 13 or 14

    if (tid == 0)
        for (int s = 0; s < STAGES; s++) mbar_init(smem_u32(&mbar[s]), 1);

    for (int L = tid; L < nch * CROWS; L += TPB) {
        int i = (slot + (L >> 3) * CTAS_PER_B) * CROWS + (L & 7);
        s_st[L] = reinterpret_cast<const float4*>(inp)[b * N + i];
    }
    __syncthreads();

    if (tid == 0) {
#pragma unroll
        for (int s = 0; s < 2 && s < nch; s++) {
            mbar_expect_tx(smem_u32(&mbar[s]), CHUNK_BYTES);
            tma_bulk_1d(smem_u32(bufs + s * CHUNK_FLOATS),
                        OD + (size_t)(slot + s * CTAS_PER_B) * CROWS * N,
                        CHUNK_BYTES, smem_u32(&mbar[s]));
        }
    }

    float4 dA[CROWS], dB[CROWS];
    float acc[4][4] = {};

    auto body = [&](float4 (&cur)[CROWS], float4 (&prv)[CROWS], int c) {
        mbar_wait(smem_u32(&mbar[c % 3]), (c / 3) & 1);
        const float4* p = reinterpret_cast<const float4*>(bufs + (c % 3) * CHUNK_FLOATS) + tid;
#pragma unroll
        for (int r = 0; r < CROWS; r++) cur[r] = p[r * (N / 4)];
#pragma unroll
        for (int r = 0; r < CROWS; r++)
            s_part[r * TPB + tid] = (cur[r].x + cur[r].y) + (cur[r].z + cur[r].w);
        // FMA on previous chunk (weights published at last barrier) — overlaps LDS
        if (c > 0) {
            const float4* wrow = &s_w[((c - 1) & 1) * CROWS];
#pragma unroll
            for (int r = 0; r < CROWS; r++) {
                float4 v = prv[r];
                float4 w = wrow[r];
                float wk[4] = {w.x, w.y, w.z, w.w};
#pragma unroll
                for (int k = 0; k < 4; k++) {
                    acc[0][k] = fmaf(v.x, wk[k], acc[0][k]);
                    acc[1][k] = fmaf(v.y, wk[k], acc[1][k]);
                    acc[2][k] = fmaf(v.z, wk[k], acc[2][k]);
                    acc[3][k] = fmaf(v.w, wk[k], acc[3][k]);
                }
            }
        }
        __syncthreads();   // bar A: partials(c) ready; buffer c fully read to regs

        if (warp < CROWS) {
            const float4* pp = reinterpret_cast<const float4*>(s_part + warp * TPB);
            float s = 0.0f;
#pragma unroll
            for (int k = 0; k < TPB / 128; k++) {
                float4 v = pp[lane + k * 32];
                s += (v.x + v.y) + (v.z + v.w);
            }
#pragma unroll
            for (int o = 16; o; o >>= 1) s += __shfl_xor_sync(0xffffffffu, s, o);
            if (lane == 0) {
                float4 f = s_st[c * CROWS + warp];
                int gi = b * N + (slot + c * CTAS_PER_B) * CROWS + warp;
                float ratio = f.x / (DELTA + s);
                float sc = ratio < 1.0f ? ratio : 1.0f;
                g_odout1[gi] = sc * s;
                float inv = 1.0f / (DELTA + f.x);
                s_w[(c & 1) * CROWS + warp] =
                    make_float4(sc, sc * (f.y * inv), sc * (f.z * inv), sc * (f.w * inv));
            }
        }
        // issue chunk c+2 into ring slot (c+2)%3 (its old data, chunk c-1,
        // was fully consumed to registers before bar A of iteration c-1)
        if (tid == 0 && c + 2 < nch) {
            mbar_expect_tx(smem_u32(&mbar[(c + 2) % 3]), CHUNK_BYTES);
            tma_bulk_1d(smem_u32(bufs + ((c + 2) % 3) * CHUNK_FLOATS),
                        OD + (size_t)(slot + (c + 2) * CTAS_PER_B) * CROWS * N,
                        CHUNK_BYTES, smem_u32(&mbar[(c + 2) % 3]));
        }
        __syncthreads();   // bar B: weights(c) published for next iteration's FMA
    };

    for (int c = 0; c < nch; c += 2) {
        body(dA, dB, c);
        if (c + 1 < nch) body(dB, dA, c + 1);
    }
    {   // epilogue: FMA on the last chunk
        float4 (&prv)[CROWS] = ((nch - 1) & 1) ? dB : dA;
        const float4* wrow = &s_w[((nch - 1) & 1) * CROWS];
#pragma unroll
        for (int r = 0; r < CROWS; r++) {
            float4 v = prv[r];
            float4 w = wrow[r];
            float wk[4] = {w.x, w.y, w.z, w.w};
#pragma unroll
            for (int k = 0; k < 4; k++) {
                acc[0][k] = fmaf(v.x, wk[k], acc[0][k]);
                acc[1][k] = fmaf(v.y, wk[k], acc[1][k]);
                acc[2][k] = fmaf(v.z, wk[k], acc[2][k]);
                acc[3][k] = fmaf(v.w, wk[k], acc[3][k]);
            }
        }
    }

#pragma unroll
    for (int cc = 0; cc < 4; cc++) {
        float* dst = g_colA + ((size_t)b * N + tid * 4 + cc) * 4;
#pragma unroll
        for (int k = 0; k < 4; k++) atomicAdd(dst + k, acc[cc][k]);
    }
}

// ---------------------------------------------------------------------------
// Pass 2 (iteration 1, K=7). Fuses update<3> in the state prefetch.
// ---------------------------------------------------------------------------
__global__ void __launch_bounds__(TPB, 1) pass2_kernel(
    const float* __restrict__ inp, const float* __restrict__ od_all)
{
    extern __shared__ float sm[];
    float*     bufs   = sm;
    float*     s_part = sm + STAGES * CHUNK_FLOATS;
    float4*    s_w    = reinterpret_cast<float4*>(s_part + CROWS * TPB); // [2][CROWS][2]
    float4*    s_st   = s_w + 2 * CROWS * 2;                             // [MAXCH*CROWS*2]
    uint64_t*  mbar   = reinterpret_cast<uint64_t*>(s_st + MAXCH * CROWS * 2);

    const int b    = blockIdx.x / CTAS_PER_B;
    const int slot = blockIdx.x % CTAS_PER_B;
    const int tid  = threadIdx.x;
    const int warp = tid >> 5, lane = tid & 31;
    const float* OD = od_all + (size_t)(b * 2 + 1) * N * N;
    const int nch = (NCHUNKS - 1 - slot) / CTAS_PER_B + 1;

    if (tid == 0)
        for (int s = 0; s < STAGES; s++) mbar_init(smem_u32(&mbar[s]), 1);

    // One-time prefetch + fused iter-0 state update; re-zero colA for replay
    for (int L = tid; L < nch * CROWS; L += TPB) {
        int i  = (slot + (L >> 3) * CTAS_PER_B) * CROWS + (L & 7);
        int gi = b * N + i;
        float4 f   = reinterpret_cast<const float4*>(inp)[gi];
        float4 csA = reinterpret_cast<float4*>(g_colA)[gi];
        reinterpret_cast<float4*>(g_colA)[gi] = make_float4(0, 0, 0, 0);
        float od1 = g_odout1[gi];
        float inv0 = 1.0f / (DELTA + f.x);
        float s60 = f.y - od1 * (f.y * inv0);
        float s61 = f.z - od1 * (f.z * inv0);
        float s62 = f.w - od1 * (f.w * inv0);
        float pop1 = f.x - od1 + csA.x;
        s_st[L * 2 + 0] = make_float4(pop1, s60, s61, s62);
        s_st[L * 2 + 1] = make_float4(csA.y, csA.z, csA.w, 0.0f);
        g_pop1[gi] = pop1;
        g_sir6[gi * 2 + 0] = make_float4(s60, s61, s62, csA.y);
        g_sir6[gi * 2 + 1] = make_float4(csA.z, csA.w, 0.0f, 0.0f);
    }
    __syncthreads();

    if (tid == 0) {
#pragma unroll
        for (int s = 0; s < 2 && s < nch; s++) {
            mbar_expect_tx(smem_u32(&mbar[s]), CHUNK_BYTES);
            tma_bulk_1d(smem_u32(bufs + s * CHUNK_FLOATS),
                        OD + (size_t)(slot + s * CTAS_PER_B) * CROWS * N,
                        CHUNK_BYTES, smem_u32(&mbar[s]));
        }
    }

    float4 dA[CROWS], dB[CROWS];
    float acc[4][7] = {};

    auto body = [&](float4 (&cur)[CROWS], float4 (&prv)[CROWS], int c) {
        mbar_wait(smem_u32(&mbar[c % 3]), (c / 3) & 1);
        const float4* p = reinterpret_cast<const float4*>(bufs + (c % 3) * CHUNK_FLOATS) + tid;
#pragma unroll
        for (int r = 0; r < CROWS; r++) cur[r] = p[r * (N / 4)];
#pragma unroll
        for (int r = 0; r < CROWS; r++)
            s_part[r * TPB + tid] = (cur[r].x + cur[r].y) + (cur[r].z + cur[r].w);
        if (c > 0) {
            const float4* wrow = &s_w[((c - 1) & 1) * CROWS * 2];
#pragma unroll
            for (int r = 0; r < CROWS; r++) {
                float4 v  = prv[r];
                float4 wa = wrow[r * 2 + 0];
                float4 wb = wrow[r * 2 + 1];
                float wk[7] = {wa.x, wa.y, wa.z, wa.w, wb.x, wb.y, wb.z};
#pragma unroll
                for (int k = 0; k < 7; k++) {
                    acc[0][k] = fmaf(v.x, wk[k], acc[0][k]);
                    acc[1][k] = fmaf(v.y, wk[k], acc[1][k]);
                    acc[2][k] = fmaf(v.z, wk[k], acc[2][k]);
                    acc[3][k] = fmaf(v.w, wk[k], acc[3][k]);
                }
            }
        }
        __syncthreads();   // bar A

        if (warp < CROWS) {
            const float4* pp = reinterpret_cast<const float4*>(s_part + warp * TPB);
            float s = 0.0f;
#pragma unroll
            for (int k = 0; k < TPB / 128; k++) {
                float4 v = pp[lane + k * 32];
                s += (v.x + v.y) + (v.z + v.w);
            }
#pragma unroll
            for (int o = 16; o; o >>= 1) s += __shfl_xor_sync(0xffffffffu, s, o);
            if (lane == 0) {
                float4 a  = s_st[(c * CROWS + warp) * 2 + 0];   // pop1, s6[0..2]
                float4 bb = s_st[(c * CROWS + warp) * 2 + 1];   // s6[3..5]
                int gi = b * N + (slot + c * CTAS_PER_B) * CROWS + warp;
                float ratio = a.x / (DELTA + s);
                float sc = ratio < 1.0f ? ratio : 1.0f;
                g_odout2[gi] = sc * s;
                float inv = 1.0f / (DELTA + a.x);
                s_w[((c & 1) * CROWS + warp) * 2 + 0] =
                    make_float4(sc, sc * (a.y * inv), sc * (a.z * inv), sc * (a.w * inv));
                s_w[((c & 1) * CROWS + warp) * 2 + 1] =
                    make_float4(sc * (bb.x * inv), sc * (bb.y * inv),
                                sc * (bb.z * inv), 0.0f);
            }
        }
        if (tid == 0 && c + 2 < nch) {
            mbar_expect_tx(smem_u32(&mbar[(c + 2) % 3]), CHUNK_BYTES);
            tma_bulk_1d(smem_u32(bufs + ((c + 2) % 3) * CHUNK_FLOATS),
                        OD + (size_t)(slot + (c + 2) * CTAS_PER_B) * CROWS * N,
                        CHUNK_BYTES, smem_u32(&mbar[(c + 2) % 3]));
        }
        __syncthreads();   // bar B
    };

    for (int c = 0; c < nch; c += 2) {
        body(dA, dB, c);
        if (c + 1 < nch) body(dB, dA, c + 1);
    }
    {   // epilogue: FMA on the last chunk
        float4 (&prv)[CROWS] = ((nch - 1) & 1) ? dB : dA;
        const float4* wrow = &s_w[((nch - 1) & 1) * CROWS * 2];
#pragma unroll
        for (int r = 0; r < CROWS; r++) {
            float4 v  = prv[r];
            float4 wa = wrow[r * 2 + 0];
            float4 wb = wrow[r * 2 + 1];
            float wk[7] = {wa.x, wa.y, wa.z, wa.w, wb.x, wb.y, wb.z};
#pragma unroll
            for (int k = 0; k < 7; k++) {
                acc[0][k] = fmaf(v.x, wk[k], acc[0][k]);
                acc[1][k] = fmaf(v.y, wk[k], acc[1][k]);
                acc[2][k] = fmaf(v.z, wk[k], acc[2][k]);
                acc[3][k] = fmaf(v.w, wk[k], acc[3][k]);
            }
        }
    }

#pragma unroll
    for (int cc = 0; cc < 4; cc++) {
        float* dst = g_colB + ((size_t)b * N + tid * 4 + cc) * 8;
#pragma unroll
        for (int k = 0; k < 7; k++) atomicAdd(dst + k, acc[cc][k]);
    }
}

// ---------------------------------------------------------------------------
// Final: fuses update<6> + GEMM(12->64) + relu + concat(pop). Re-zeros colB.
// ---------------------------------------------------------------------------
__global__ void __launch_bounds__(256) final_kernel(
    const float* __restrict__ kern,
    const float* __restrict__ bias,
    float* __restrict__ out)
{
    __shared__ float s_kern[12 * 64];
    const int tid = threadIdx.x;
    for (int t = tid; t < 12 * 64; t += 256) s_kern[t] = kern[t];
    __syncthreads();

    const int rowl = tid >> 6;
    const int c    = tid & 63;
    const int gi   = blockIdx.x * 4 + rowl;

    float pop1   = g_pop1[gi];
    float odout2 = g_odout2[gi];
    float4 a   = g_sir6[gi * 2 + 0];
    float4 b4  = g_sir6[gi * 2 + 1];
    float4 cb0 = reinterpret_cast<const float4*>(g_colB)[gi * 2 + 0];
    float4 cb1 = reinterpret_cast<const float4*>(g_colB)[gi * 2 + 1];

    float dp1 = DELTA + pop1;
    float s12[12];
    s12[0] = a.x  - odout2 * dnn(a.x,  dp1);
    s12[1] = a.y  - odout2 * dnn(a.y,  dp1);
    s12[2] = a.z  - odout2 * dnn(a.z,  dp1);
    s12[3] = a.w  - odout2 * dnn(a.w,  dp1);
    s12[4] = b4.x - odout2 * dnn(b4.x, dp1);
    s12[5] = b4.y - odout2 * dnn(b4.y, dp1);
    s12[6]  = cb0.y; s12[7]  = cb0.z; s12[8]  = cb0.w;
    s12[9]  = cb1.x; s12[10] = cb1.y; s12[11] = cb1.z;

    float acc = __ldg(&bias[c]);
#pragma unroll
    for (int f = 0; f < 12; f++)
        acc = fmaf(s12[f], s_kern[f * 64 + c], acc);
    acc = fmaxf(acc, 0.0f);

    float* orow = out + (size_t)gi * 65;
    orow[1 + c] = acc;
    if (c == 0) orow[0] = pop1 - odout2 + cb0.x;

    __syncthreads();                  // all colB reads done before re-zero
    if (c < 8) g_colB[gi * 8 + c] = 0.0f;
}

// ---------------------------------------------------------------------------
extern "C" void kernel_launch(void* const* d_in, const int* in_sizes, int n_in,
                              void* d_out, int out_size) {
    const float* inp  = (const float*)d_in[0];  // input_feature (8,2048,4)
    const float* od   = (const float*)d_in[1];  // OD_all (8,2,2048,2048)
    const float* kern = (const float*)d_in[2];  // kernel (12,64)
    const float* bias = (const float*)d_in[3];  // bias (64)
    float* out = (float*)d_out;                 // (8,2048,65)

    const int SMEM1 = STAGES * CHUNK_FLOATS * 4 + CROWS * TPB * 4
                    + 2 * CROWS * 16 + MAXCH * CROWS * 16 + 64;
    const int SMEM2 = STAGES * CHUNK_FLOATS * 4 + CROWS * TPB * 4
                    + 2 * CROWS * 2 * 16 + MAXCH * CROWS * 32 + 64;

    cudaFuncSetAttribute(pass1_kernel, cudaFuncAttributeMaxDynamicSharedMemorySize, SMEM1);
    cudaFuncSetAttribute(pass2_kernel, cudaFuncAttributeMaxDynamicSharedMemorySize, SMEM2);

    pass1_kernel<<<GRID, TPB, SMEM1>>>(inp, od);
    pass2_kernel<<<GRID, TPB, SMEM2>>>(inp, od);
    final_kernel<<<BN / 4, 256>>>(kern, bias, out);
}

// round 10
// speedup vs baseline: 1.0015x; 1.0015x over previous
#include <cuda_runtime.h>
#include <cstdint>

#define B 8
#define N 2048
#define BN (B * N)
#define DELTA 1e-7f

#define TPB 512
#define NWARP (TPB / 32)
#define CROWS 8                         // rows per chunk: 8*2048*4B = 64KB contiguous
#define CHUNK_FLOATS (CROWS * N)        // 16384 floats
#define CHUNK_BYTES (CHUNK_FLOATS * 4)  // 65536
#define NCHUNKS (N / CROWS)             // 256 chunks per batch
#define CTAS_PER_B 19
#define GRID (B * CTAS_PER_B)           // 152 CTAs = GB300 SM count
#define STAGES 3
#define MAXCH ((NCHUNKS + CTAS_PER_B - 1) / CTAS_PER_B)   // 14

// Persistent scratch (__device__ globals per allocation rules).
__device__ float  g_odout1[BN];
__device__ float  g_odout2[BN];
__device__ float  g_pop1[BN];
__device__ float4 g_sir6[BN * 2];   // SIR after iter 0 (6 floats in 2x float4)
__device__ float  g_colA[BN * 4];   // iter0 colsums [OD_in, SIR_in*3] (zeroed by pass2)
__device__ float  g_colB[BN * 8];   // iter1 colsums [OD_in, SIR_in*6, pad] (zeroed by final)

__device__ __forceinline__ float dnn(float n, float d) { return (d == 0.0f) ? 0.0f : n / d; }

__device__ __forceinline__ uint32_t smem_u32(const void* p) {
    return (uint32_t)__cvta_generic_to_shared(p);
}
__device__ __forceinline__ void mbar_init(uint32_t a, uint32_t cnt) {
    asm volatile("mbarrier.init.shared.b64 [%0], %1;" :: "r"(a), "r"(cnt) : "memory");
}
__device__ __forceinline__ void mbar_expect_tx(uint32_t a, uint32_t bytes) {
    asm volatile("mbarrier.arrive.expect_tx.shared.b64 _, [%0], %1;"
                 :: "r"(a), "r"(bytes) : "memory");
}
__device__ __forceinline__ void mbar_wait(uint32_t a, uint32_t parity) {
    asm volatile(
        "{\n\t.reg .pred P;\n"
        "WAIT_%=:\n\t"
        "mbarrier.try_wait.parity.acquire.cta.shared::cta.b64 P, [%0], %1, 0x989680;\n\t"
        "@P bra DONE_%=;\n\t"
        "bra WAIT_%=;\n"
        "DONE_%=:\n\t}"
        :: "r"(a), "r"(parity) : "memory");
}
__device__ __forceinline__ void tma_bulk_1d(uint32_t dst, const void* src,
                                            uint32_t bytes, uint32_t mbar) {
    asm volatile(
        "cp.async.bulk.shared::cta.global.mbarrier::complete_tx::bytes [%0], [%1], %2, [%3];"
        :: "r"(dst), "l"(src), "r"(bytes), "r"(mbar) : "memory");
}

// ---------------------------------------------------------------------------
// Pass 1 (iteration 0, K=4). TMA ring, single barrier per chunk.
// ---------------------------------------------------------------------------
__global__ void __launch_bounds__(TPB, 1) pass1_kernel(
    const float* __restrict__ inp, const float* __restrict__ od_all)
{
    extern __shared__ float sm[];
    float*    bufs  = sm;                                           // [3][16384]
    float*    s_sum = sm + STAGES * CHUNK_FLOATS;                   // [2][CROWS*NWARP]
    float4*   s_w   = reinterpret_cast<float4*>(s_sum + 2 * CROWS * NWARP); // [2][CROWS]
    float4*   s_st  = s_w + 2 * CROWS;                              // [MAXCH*CROWS]
    uint64_t* mbar  = reinterpret_cast<uint64_t*>(s_st + MAXCH * CROWS);    // [3]

    const int b    = blockIdx.x / CTAS_PER_B;
    const int slot = blockIdx.x % CTAS_PER_B;
    const int tid  = threadIdx.x;
    const int warp = tid >> 5, lane = tid & 31;
    const float* OD = od_all + (size_t)(b * 2) * N * N;
    const int nch = (NCHUNKS - 1 - slot) / CTAS_PER_B + 1;   // 13 or 14

    if (tid == 0)
        for (int s = 0; s < STAGES; s++) mbar_init(smem_u32(&mbar[s]), 1);

    for (int L = tid; L < nch * CROWS; L += TPB) {
        int i = (slot + (L >> 3) * CTAS_PER_B) * CROWS + (L & 7);
        s_st[L] = reinterpret_cast<const float4*>(inp)[b * N + i];
    }
    __syncthreads();

    if (tid == 0) {
#pragma unroll
        for (int s = 0; s < 2; s++) {
            mbar_expect_tx(smem_u32(&mbar[s]), CHUNK_BYTES);
            tma_bulk_1d(smem_u32(bufs + s * CHUNK_FLOATS),
                        OD + (size_t)(slot + s * CTAS_PER_B) * CROWS * N,
                        CHUNK_BYTES, smem_u32(&mbar[s]));
        }
    }

    float4 dA[CROWS], dB[CROWS];
    float acc[4][4] = {};

    auto body = [&](float4 (&cur)[CROWS], float4 (&prv)[CROWS], int c) {
        // ---- pre-bar: load chunk c to regs, warp-shfl row partials ----
        mbar_wait(smem_u32(&mbar[c % 3]), (c / 3) & 1);
        const float4* p = reinterpret_cast<const float4*>(bufs + (c % 3) * CHUNK_FLOATS) + tid;
#pragma unroll
        for (int r = 0; r < CROWS; r++) cur[r] = p[r * (N / 4)];
        float* sum_buf = s_sum + (c & 1) * CROWS * NWARP;
#pragma unroll
        for (int r = 0; r < CROWS; r++) {
            float s = (cur[r].x + cur[r].y) + (cur[r].z + cur[r].w);
#pragma unroll
            for (int o = 16; o; o >>= 1) s += __shfl_xor_sync(0xffffffffu, s, o);
            if (lane == 0) sum_buf[r * NWARP + warp] = s;
        }
        __syncthreads();   // the ONLY barrier per chunk

        // ---- post-bar: reduce(c) -> s_w[c&1] (warps<8); all warps FMA(c-1) ----
        if (warp < CROWS) {
            float s = (lane < NWARP) ? sum_buf[warp * NWARP + lane] : 0.0f;
#pragma unroll
            for (int o = 8; o; o >>= 1) s += __shfl_xor_sync(0xffffffffu, s, o);
            if (lane == 0) {
                float4 f = s_st[c * CROWS + warp];
                int gi = b * N + (slot + c * CTAS_PER_B) * CROWS + warp;
                float ratio = f.x / (DELTA + s);
                float sc = ratio < 1.0f ? ratio : 1.0f;
                g_odout1[gi] = sc * s;
                float inv = 1.0f / (DELTA + f.x);
                s_w[(c & 1) * CROWS + warp] =
                    make_float4(sc, sc * (f.y * inv), sc * (f.z * inv), sc * (f.w * inv));
            }
        }
        if (tid == TPB - 1 && c + 2 < nch) {   // issue chunk c+2 (slot held chunk c-1, long consumed)
            mbar_expect_tx(smem_u32(&mbar[(c + 2) % 3]), CHUNK_BYTES);
            tma_bulk_1d(smem_u32(bufs + ((c + 2) % 3) * CHUNK_FLOATS),
                        OD + (size_t)(slot + (c + 2) * CTAS_PER_B) * CROWS * N,
                        CHUNK_BYTES, smem_u32(&mbar[(c + 2) % 3]));
        }
        if (c > 0) {
            const float4* wrow = &s_w[((c - 1) & 1) * CROWS];   // written post-bar(c-1), ordered by bar(c)
#pragma unroll
            for (int r = 0; r < CROWS; r++) {
                float4 v = prv[r];
                float4 w = wrow[r];
                float wk[4] = {w.x, w.y, w.z, w.w};
#pragma unroll
                for (int k = 0; k < 4; k++) {
                    acc[0][k] = fmaf(v.x, wk[k], acc[0][k]);
                    acc[1][k] = fmaf(v.y, wk[k], acc[1][k]);
                    acc[2][k] = fmaf(v.z, wk[k], acc[2][k]);
                    acc[3][k] = fmaf(v.w, wk[k], acc[3][k]);
                }
            }
        }
    };

    for (int c = 0; c < nch; c += 2) {
        body(dA, dB, c);
        if (c + 1 < nch) body(dB, dA, c + 1);
    }
    __syncthreads();   // order reduce(nch-1)'s s_w writes before epilogue FMA
    {
        float4 (&prv)[CROWS] = ((nch - 1) & 1) ? dB : dA;
        const float4* wrow = &s_w[((nch - 1) & 1) * CROWS];
#pragma unroll
        for (int r = 0; r < CROWS; r++) {
            float4 v = prv[r];
            float4 w = wrow[r];
            float wk[4] = {w.x, w.y, w.z, w.w};
#pragma unroll
            for (int k = 0; k < 4; k++) {
                acc[0][k] = fmaf(v.x, wk[k], acc[0][k]);
                acc[1][k] = fmaf(v.y, wk[k], acc[1][k]);
                acc[2][k] = fmaf(v.z, wk[k], acc[2][k]);
                acc[3][k] = fmaf(v.w, wk[k], acc[3][k]);
            }
        }
    }

#pragma unroll
    for (int cc = 0; cc < 4; cc++) {
        float* dst = g_colA + ((size_t)b * N + tid * 4 + cc) * 4;
#pragma unroll
        for (int k = 0; k < 4; k++) atomicAdd(dst + k, acc[cc][k]);
    }
}

// ---------------------------------------------------------------------------
// Pass 2 (iteration 1, K=7). Fuses update<3> in the state prefetch.
// ---------------------------------------------------------------------------
__global__ void __launch_bounds__(TPB, 1) pass2_kernel(
    const float* __restrict__ inp, const float* __restrict__ od_all)
{
    extern __shared__ float sm[];
    float*    bufs  = sm;
    float*    s_sum = sm + STAGES * CHUNK_FLOATS;                   // [2][CROWS*NWARP]
    float4*   s_w   = reinterpret_cast<float4*>(s_sum + 2 * CROWS * NWARP); // [2][CROWS][2]
    float4*   s_st  = s_w + 2 * CROWS * 2;                          // [MAXCH*CROWS*2]
    uint64_t* mbar  = reinterpret_cast<uint64_t*>(s_st + MAXCH * CROWS * 2);

    const int b    = blockIdx.x / CTAS_PER_B;
    const int slot = blockIdx.x % CTAS_PER_B;
    const int tid  = threadIdx.x;
    const int warp = tid >> 5, lane = tid & 31;
    const float* OD = od_all + (size_t)(b * 2 + 1) * N * N;
    const int nch = (NCHUNKS - 1 - slot) / CTAS_PER_B + 1;

    if (tid == 0)
        for (int s = 0; s < STAGES; s++) mbar_init(smem_u32(&mbar[s]), 1);

    // One-time prefetch + fused iter-0 state update; re-zero colA for replay
    for (int L = tid; L < nch * CROWS; L += TPB) {
        int i  = (slot + (L >> 3) * CTAS_PER_B) * CROWS + (L & 7);
        int gi = b * N + i;
        float4 f   = reinterpret_cast<const float4*>(inp)[gi];
        float4 csA = reinterpret_cast<float4*>(g_colA)[gi];
        reinterpret_cast<float4*>(g_colA)[gi] = make_float4(0, 0, 0, 0);
        float od1 = g_odout1[gi];
        float inv0 = 1.0f / (DELTA + f.x);
        float s60 = f.y - od1 * (f.y * inv0);
        float s61 = f.z - od1 * (f.z * inv0);
        float s62 = f.w - od1 * (f.w * inv0);
        float pop1 = f.x - od1 + csA.x;
        s_st[L * 2 + 0] = make_float4(pop1, s60, s61, s62);
        s_st[L * 2 + 1] = make_float4(csA.y, csA.z, csA.w, 0.0f);
        g_pop1[gi] = pop1;
        g_sir6[gi * 2 + 0] = make_float4(s60, s61, s62, csA.y);
        g_sir6[gi * 2 + 1] = make_float4(csA.z, csA.w, 0.0f, 0.0f);
    }
    __syncthreads();

    if (tid == 0) {
#pragma unroll
        for (int s = 0; s < 2; s++) {
            mbar_expect_tx(smem_u32(&mbar[s]), CHUNK_BYTES);
            tma_bulk_1d(smem_u32(bufs + s * CHUNK_FLOATS),
                        OD + (size_t)(slot + s * CTAS_PER_B) * CROWS * N,
                        CHUNK_BYTES, smem_u32(&mbar[s]));
        }
    }

    float4 dA[CROWS], dB[CROWS];
    float acc[4][7] = {};

    auto body = [&](float4 (&cur)[CROWS], float4 (&prv)[CROWS], int c) {
        mbar_wait(smem_u32(&mbar[c % 3]), (c / 3) & 1);
        const float4* p = reinterpret_cast<const float4*>(bufs + (c % 3) * CHUNK_FLOATS) + tid;
#pragma unroll
        for (int r = 0; r < CROWS; r++) cur[r] = p[r * (N / 4)];
        float* sum_buf = s_sum + (c & 1) * CROWS * NWARP;
#pragma unroll
        for (int r = 0; r < CROWS; r++) {
            float s = (cur[r].x + cur[r].y) + (cur[r].z + cur[r].w);
#pragma unroll
            for (int o = 16; o; o >>= 1) s += __shfl_xor_sync(0xffffffffu, s, o);
            if (lane == 0) sum_buf[r * NWARP + warp] = s;
        }
        __syncthreads();

        if (warp < CROWS) {
            float s = (lane < NWARP) ? sum_buf[warp * NWARP + lane] : 0.0f;
#pragma unroll
            for (int o = 8; o; o >>= 1) s += __shfl_xor_sync(0xffffffffu, s, o);
            if (lane == 0) {
                float4 a  = s_st[(c * CROWS + warp) * 2 + 0];   // pop1, s6[0..2]
                float4 bb = s_st[(c * CROWS + warp) * 2 + 1];   // s6[3..5]
                int gi = b * N + (slot + c * CTAS_PER_B) * CROWS + warp;
                float ratio = a.x / (DELTA + s);
                float sc = ratio < 1.0f ? ratio : 1.0f;
                g_odout2[gi] = sc * s;
                float inv = 1.0f / (DELTA + a.x);
                s_w[((c & 1) * CROWS + warp) * 2 + 0] =
                    make_float4(sc, sc * (a.y * inv), sc * (a.z * inv), sc * (a.w * inv));
                s_w[((c & 1) * CROWS + warp) * 2 + 1] =
                    make_float4(sc * (bb.x * inv), sc * (bb.y * inv),
                                sc * (bb.z * inv), 0.0f);
            }
        }
        if (tid == TPB - 1 && c + 2 < nch) {
            mbar_expect_tx(smem_u32(&mbar[(c + 2) % 3]), CHUNK_BYTES);
            tma_bulk_1d(smem_u32(bufs + ((c + 2) % 3) * CHUNK_FLOATS),
                        OD + (size_t)(slot + (c + 2) * CTAS_PER_B) * CROWS * N,
                        CHUNK_BYTES, smem_u32(&mbar[(c + 2) % 3]));
        }
        if (c > 0) {
            const float4* wrow = &s_w[((c - 1) & 1) * CROWS * 2];
#pragma unroll
            for (int r = 0; r < CROWS; r++) {
                float4 v  = prv[r];
                float4 wa = wrow[r * 2 + 0];
                float4 wb = wrow[r * 2 + 1];
                float wk[7] = {wa.x, wa.y, wa.z, wa.w, wb.x, wb.y, wb.z};
#pragma unroll
                for (int k = 0; k < 7; k++) {
                    acc[0][k] = fmaf(v.x, wk[k], acc[0][k]);
                    acc[1][k] = fmaf(v.y, wk[k], acc[1][k]);
                    acc[2][k] = fmaf(v.z, wk[k], acc[2][k]);
                    acc[3][k] = fmaf(v.w, wk[k], acc[3][k]);
                }
            }
        }
    };

    for (int c = 0; c < nch; c += 2) {
        body(dA, dB, c);
        if (c + 1 < nch) body(dB, dA, c + 1);
    }
    __syncthreads();
    {
        float4 (&prv)[CROWS] = ((nch - 1) & 1) ? dB : dA;
        const float4* wrow = &s_w[((nch - 1) & 1) * CROWS * 2];
#pragma unroll
        for (int r = 0; r < CROWS; r++) {
            float4 v  = prv[r];
            float4 wa = wrow[r * 2 + 0];
            float4 wb = wrow[r * 2 + 1];
            float wk[7] = {wa.x, wa.y, wa.z, wa.w, wb.x, wb.y, wb.z};
#pragma unroll
            for (int k = 0; k < 7; k++) {
                acc[0][k] = fmaf(v.x, wk[k], acc[0][k]);
                acc[1][k] = fmaf(v.y, wk[k], acc[1][k]);
                acc[2][k] = fmaf(v.z, wk[k], acc[2][k]);
                acc[3][k] = fmaf(v.w, wk[k], acc[3][k]);
            }
        }
    }

#pragma unroll
    for (int cc = 0; cc < 4; cc++) {
        float* dst = g_colB + ((size_t)b * N + tid * 4 + cc) * 8;
#pragma unroll
        for (int k = 0; k < 7; k++) atomicAdd(dst + k, acc[cc][k]);
    }
}

// ---------------------------------------------------------------------------
// Final: fuses update<6> + GEMM(12->64) + relu + concat(pop). Re-zeros colB.
// ---------------------------------------------------------------------------
__global__ void __launch_bounds__(256) final_kernel(
    const float* __restrict__ kern,
    const float* __restrict__ bias,
    float* __restrict__ out)
{
    __shared__ float s_kern[12 * 64];
    const int tid = threadIdx.x;
    for (int t = tid; t < 12 * 64; t += 256) s_kern[t] = kern[t];
    __syncthreads();

    const int rowl = tid >> 6;
    const int c    = tid & 63;
    const int gi   = blockIdx.x * 4 + rowl;

    float pop1   = g_pop1[gi];
    float odout2 = g_odout2[gi];
    float4 a   = g_sir6[gi * 2 + 0];
    float4 b4  = g_sir6[gi * 2 + 1];
    float4 cb0 = reinterpret_cast<const float4*>(g_colB)[gi * 2 + 0];
    float4 cb1 = reinterpret_cast<const float4*>(g_colB)[gi * 2 + 1];

    float dp1 = DELTA + pop1;
    float s12[12];
    s12[0] = a.x  - odout2 * dnn(a.x,  dp1);
    s12[1] = a.y  - odout2 * dnn(a.y,  dp1);
    s12[2] = a.z  - odout2 * dnn(a.z,  dp1);
    s12[3] = a.w  - odout2 * dnn(a.w,  dp1);
    s12[4] = b4.x - odout2 * dnn(b4.x, dp1);
    s12[5] = b4.y - odout2 * dnn(b4.y, dp1);
    s12[6]  = cb0.y; s12[7]  = cb0.z; s12[8]  = cb0.w;
    s12[9]  = cb1.x; s12[10] = cb1.y; s12[11] = cb1.z;

    float acc = __ldg(&bias[c]);
#pragma unroll
    for (int f = 0; f < 12; f++)
        acc = fmaf(s12[f], s_kern[f * 64 + c], acc);
    acc = fmaxf(acc, 0.0f);

    float* orow = out + (size_t)gi * 65;
    orow[1 + c] = acc;
    if (c == 0) orow[0] = pop1 - odout2 + cb0.x;

    __syncthreads();                  // all colB reads done before re-zero
    if (c < 8) g_colB[gi * 8 + c] = 0.0f;
}

// ---------------------------------------------------------------------------
extern "C" void kernel_launch(void* const* d_in, const int* in_sizes, int n_in,
                              void* d_out, int out_size) {
    const float* inp  = (const float*)d_in[0];  // input_feature (8,2048,4)
    const float* od   = (const float*)d_in[1];  // OD_all (8,2,2048,2048)
    const float* kern = (const float*)d_in[2];  // kernel (12,64)
    const float* bias = (const float*)d_in[3];  // bias (64)
    float* out = (float*)d_out;                 // (8,2048,65)

    const int SMEM1 = STAGES * CHUNK_FLOATS * 4 + 2 * CROWS * NWARP * 4
                    + 2 * CROWS * 16 + MAXCH * CROWS * 16 + 64;
    const int SMEM2 = STAGES * CHUNK_FLOATS * 4 + 2 * CROWS * NWARP * 4
                    + 2 * CROWS * 2 * 16 + MAXCH * CROWS * 32 + 64;

    cudaFuncSetAttribute(pass1_kernel, cudaFuncAttributeMaxDynamicSharedMemorySize, SMEM1);
    cudaFuncSetAttribute(pass2_kernel, cudaFuncAttributeMaxDynamicSharedMemorySize, SMEM2);

    pass1_kernel<<<GRID, TPB, SMEM1>>>(inp, od);
    pass2_kernel<<<GRID, TPB, SMEM2>>>(inp, od);
    final_kernel<<<BN / 4, 256>>>(kern, bias, out);
}